// round 14
// baseline (speedup 1.0000x reference)
#include <cuda_runtime.h>
#include <cuda_fp16.h>
#include <cstdint>

#define TPB  128
#define ROWS 23     // grid = ceil(16384/23) = 713 <= 148 SMs * 5 CTAs = 740 -> single wave
#define LVL  6
#define DIRD 16
#define HD   64

// ---- dynamic smem offsets (bytes) ----
#define BF_OFF    0u        // B-fragment table: 48 slots * 32 lanes * 8B = 12288
#define A0_OFF    12288u    // A0 fp16 tile: 128 rows * 80B = 10240
#define W0D_OFF   22528u    // W0 dir part fp32 [16][64] = 4096
#define W2S_OFF   26624u    // W2 as float4[64] = 1024
#define BIAS0_OFF 27648u    // bias' partial k0..7 (+b0) fp32[64]
#define BIAS1_OFF 27904u    // bias' partial k8..15 fp32[64]
#define B0S_OFF   28160u
#define B1S_OFF   28416u
#define SS0_OFF   28672u    // fp32[128]
#define WRED_OFF  29184u    // fp32[4]
#define CRED_OFF  29200u    // fp32[12]
#define SB2_OFF   29248u    // fp32[4]
#define STG_OFF   29264u    // gather staging: 128 threads * 112B (6 x float4, padded) = 14336
#define SMEM_TOTAL 43600u

#define STG_STRIDE 112      // 7*16B: conflict-free LDS.128 read-back
#define A0_PITCH_U32 20     // 80B pitch (conflict-free fragment loads)

__device__ __forceinline__ uint32_t packh2(float f0, float f1) {
    __half2 h = __floats2half2_rn(f0, f1);
    return *(uint32_t*)&h;
}

__device__ __forceinline__ uint32_t smem_u32(const void* p) {
    uint32_t a;
    asm("{ .reg .u64 t; cvta.to.shared.u64 t, %1; cvt.u32.u64 %0, t; }" : "=r"(a) : "l"(p));
    return a;
}

__device__ __forceinline__ void mma_fp16(float d[4], const uint32_t a[4], uint2 b) {
    asm volatile("mma.sync.aligned.m16n8k16.row.col.f32.f16.f16.f32 "
        "{%0,%1,%2,%3}, {%4,%5,%6,%7}, {%8,%9}, {%0,%1,%2,%3};"
        : "+f"(d[0]), "+f"(d[1]), "+f"(d[2]), "+f"(d[3])
        : "r"(a[0]), "r"(a[1]), "r"(a[2]), "r"(a[3]), "r"(b.x), "r"(b.y));
}

// eviction-policy registers (createpolicy + cache_hint form)
__device__ __forceinline__ uint64_t mk_policy_evict_last() {
    uint64_t p;
    asm("createpolicy.fractional.L2::evict_last.b64 %0, 1.0;" : "=l"(p));
    return p;
}
__device__ __forceinline__ uint64_t mk_policy_evict_first() {
    uint64_t p;
    asm("createpolicy.fractional.L2::evict_first.b64 %0, 1.0;" : "=l"(p));
    return p;
}

__device__ __forceinline__ int2 ldg_ef_v2(const int* p, uint64_t pol) {
    int2 v;
    asm volatile("ld.global.nc.L2::cache_hint.v2.s32 {%0, %1}, [%2], %3;"
                 : "=r"(v.x), "=r"(v.y) : "l"(p), "l"(pol));
    return v;
}
__device__ __forceinline__ float4 ldg_ef_v4f(const float* p, uint64_t pol) {
    float4 v;
    asm volatile("ld.global.nc.L2::cache_hint.v4.f32 {%0, %1, %2, %3}, [%4], %5;"
                 : "=f"(v.x), "=f"(v.y), "=f"(v.z), "=f"(v.w) : "l"(p), "l"(pol));
    return v;
}
// streaming stores: evict_first so outputs never displace the gather table
__device__ __forceinline__ void stg_ef(float* p, float v, uint64_t pol) {
    asm volatile("st.global.L2::cache_hint.f32 [%0], %1, %2;"
                 :: "l"(p), "f"(v), "l"(pol) : "memory");
}

// async 16B gather: global->smem, no register residency, L1 bypass, table pinned in L2
__device__ __forceinline__ void cpa16(uint32_t saddr, const void* g, uint64_t pol) {
    asm volatile("cp.async.cg.shared.global.L2::cache_hint [%0], [%1], 16, %2;"
                 :: "r"(saddr), "l"(g), "l"(pol) : "memory");
}
#define CPA_COMMIT() asm volatile("cp.async.commit_group;" ::: "memory")
#define CPA_WAIT0()  asm volatile("cp.async.wait_group 0;" ::: "memory")

__device__ __forceinline__ void load_idx(const int* __restrict__ xp, int* idx, uint64_t pol) {
    const int2 a = ldg_ef_v2(xp, pol);
    const int2 b = ldg_ef_v2(xp + 2, pol);
    const int2 c = ldg_ef_v2(xp + 4, pol);
    idx[0] = a.x; idx[1] = a.y; idx[2] = b.x; idx[3] = b.y; idx[4] = c.x; idx[5] = c.y;
}

__device__ __forceinline__ void gather6_async(const float4* __restrict__ gw,
                                              const int* idx, uint32_t stg, uint64_t pol) {
    #pragma unroll
    for (int l = 0; l < LVL; ++l) cpa16(stg + l * 16, gw + idx[l], pol);
    CPA_COMMIT();
}

__global__ __launch_bounds__(TPB, 5) void surf_mma(
    const int*    __restrict__ x,
    const float*  __restrict__ dirs,
    const float4* __restrict__ gw,
    const float*  __restrict__ W0, const float* __restrict__ b0,
    const float*  __restrict__ W1, const float* __restrict__ b1,
    const float*  __restrict__ W2, const float* __restrict__ b2,
    float* __restrict__ outSig, float* __restrict__ outCol, int Btot)
{
    extern __shared__ char sm[];
    const int tid = threadIdx.x, lane = tid & 31, wid = tid >> 5;
    const int g = lane >> 2, tg = lane & 3;
    const uint64_t polL = mk_policy_evict_last();
    const uint64_t polF = mk_policy_evict_first();
    const uint32_t stg = smem_u32(sm + STG_OFF) + tid * STG_STRIDE;
    const int half = tid >> 6, hn = tid & 63;   // bias-chain split

    // ================= one-time staging per CTA =================
    for (int i = tid; i < DIRD * HD; i += TPB)
        ((float*)(sm + W0D_OFF))[i] = W0[i];
    if (tid < HD) {
        float4 v; v.x = W2[tid * 3]; v.y = W2[tid * 3 + 1]; v.z = W2[tid * 3 + 2]; v.w = 0.f;
        ((float4*)(sm + W2S_OFF))[tid] = v;
        ((float*)(sm + B0S_OFF))[tid] = b0[tid];
        ((float*)(sm + B1S_OFF))[tid] = b1[tid];
    }
    if (tid < 3) ((float*)(sm + SB2_OFF))[tid] = b2[tid];

    // B fragments (fp16): layer0 slots 0..15 (ks*8+j), layer1 slots 16..47 (16+ks*8+j)
    uint2* bf = (uint2*)(sm + BF_OFF);
    for (int e = tid; e < 48 * 32; e += TPB) {
        const int s = e >> 5, ln = e & 31;
        const int lg = ln >> 2, ltg = ln & 3;
        int layer, ks, j;
        if (s < 16) { layer = 0; ks = s >> 3; j = s & 7; }
        else { const int t2 = s - 16; layer = 1; ks = t2 >> 3; j = t2 & 7; }
        const int n = j * 8 + lg;
        uint32_t regs[2];
        #pragma unroll
        for (int rr = 0; rr < 2; ++rr) {
            const int k0 = ks * 16 + ltg * 2 + rr * 8;
            float wa, wb;
            if (layer == 0) {
                wa = (k0     < 18) ? W0[(16 + k0)     * HD + n] : 0.f;
                wb = (k0 + 1 < 18) ? W0[(16 + k0 + 1) * HD + n] : 0.f;
            } else {
                wa = W1[k0 * HD + n];
                wb = W1[(k0 + 1) * HD + n];
            }
            regs[rr] = packh2(wa, wb);
        }
        uint2 v; v.x = regs[0]; v.y = regs[1];
        bf[s * 32 + ln] = v;
    }
    // zero A0 pad columns 18..31 (u32 idx 9..15)
    for (int e = tid; e < TPB * 7; e += TPB) {
        const int p = e / 7, kk = 9 + (e % 7);
        ((uint32_t*)(sm + A0_OFF))[p * A0_PITCH_U32 + kk] = 0u;
    }
    __syncthreads();

    // ================= pipelined row loop (2 barriers/row) =================
    const int bBase = blockIdx.x * ROWS;
    int nidx[LVL];
    float4 dv0, dv1;   // prefetched dirs (this thread's 8-value half) for current row
    {
        const int b0r = (bBase < Btot) ? bBase : (Btot - 1);
        load_idx(x + ((long long)b0r * TPB + tid) * LVL, nidx, polF);
        gather6_async(gw, nidx, stg, polL);
        const float* dp = dirs + b0r * DIRD + half * 8;
        dv0 = ldg_ef_v4f(dp, polF);
        dv1 = ldg_ef_v4f(dp + 4, polF);
    }

    for (int r = 0; r < ROWS; ++r) {
        int b = bBase + r;
        if (b >= Btot) b = Btot - 1;   // duplicated identical work; uniform barriers

        // prefetch next row's indices early (consumed after sync [B])
        const bool more = (r + 1 < ROWS);
        int bn = bBase + r + 1;
        if (bn >= Btot) bn = Btot - 1;
        if (more) load_idx(x + ((long long)bn * TPB + tid) * LVL, nidx, polF);

        // ---- bias' chain FIRST (gather-independent): overlaps cp.async latency ----
        {
            float acc = half ? 0.f : ((const float*)(sm + B0S_OFF))[hn];
            const float* wd = (const float*)(sm + W0D_OFF) + (half * 8) * HD + hn;
            acc += dv0.x * wd[0 * HD] + dv0.y * wd[1 * HD]
                 + dv0.z * wd[2 * HD] + dv0.w * wd[3 * HD]
                 + dv1.x * wd[4 * HD] + dv1.y * wd[5 * HD]
                 + dv1.z * wd[6 * HD] + dv1.w * wd[7 * HD];
            ((float*)(sm + (half ? BIAS1_OFF : BIAS0_OFF)))[hn] = acc;
        }
        // prefetch next row's dirs into registers (consumed next iteration)
        if (more) {
            const float* dp = dirs + bn * DIRD + half * 8;
            dv0 = ldg_ef_v4f(dp, polF);
            dv1 = ldg_ef_v4f(dp + 4, polF);
        }

        // ---- wait for own staged gathers; density + A0 pack in one pass ----
        CPA_WAIT0();
        float s = 1.f;
        {
            const float4* st4 = (const float4*)(sm + STG_OFF + tid * STG_STRIDE);
            uint32_t* ar = (uint32_t*)(sm + A0_OFF) + tid * A0_PITCH_U32;
            #pragma unroll
            for (int t = 0; t < 3; ++t) {
                const float4 a0 = st4[2 * t];
                const float4 a1 = st4[2 * t + 1];
                s *= fminf(fmaxf(a0.x, 0.f), 1.f) * fminf(fmaxf(a1.x, 0.f), 1.f);
                ar[3 * t + 0] = packh2(a0.y, a0.z);
                ar[3 * t + 1] = packh2(a0.w, a1.y);
                ar[3 * t + 2] = packh2(a1.z, a1.w);
            }
        }
        s += 1e-4f;
        ((float*)(sm + SS0_OFF))[tid] = s;
        float m = s;
        #pragma unroll
        for (int o = 16; o; o >>= 1) m = fmaxf(m, __shfl_xor_sync(0xffffffffu, m, o));
        if (lane == 0) ((float*)(sm + WRED_OFF))[wid] = m;
        __syncthreads();   // [B] — the only mid-row barrier

        // issue next row's async gathers now (own slots already consumed pre-[B])
        if (more) gather6_async(gw, nidx, stg, polL);

        // ---- sigma finalize (uses warp maxes published pre-[B]) ----
        float inv_m;
        {
            const float* wr = (const float*)(sm + WRED_OFF);
            const float mm = fmaxf(fmaxf(wr[0], wr[1]), fmaxf(wr[2], wr[3]));
            inv_m = 1.f / mm;
        }
        stg_ef(outSig + (long long)b * TPB + tid, s * inv_m, polF);

        // ================= per-warp GEMM chain (32 points/warp) =================
        float pc[2][2][3];
        #pragma unroll
        for (int a = 0; a < 2; ++a)
            #pragma unroll
            for (int q = 0; q < 2; ++q) { pc[a][q][0] = 0.f; pc[a][q][1] = 0.f; pc[a][q][2] = 0.f; }

        #pragma unroll
        for (int mt = 0; mt < 2; ++mt) {
            const int P0 = wid * 32 + mt * 16;

            uint32_t ah[2][4];
            #pragma unroll
            for (int ks = 0; ks < 2; ++ks)
                #pragma unroll
                for (int rr = 0; rr < 4; ++rr) {
                    const int row = P0 + g + ((rr & 1) << 3);
                    const int ku  = ks * 8 + tg + ((rr >> 1) << 2);
                    ah[ks][rr] = ((const uint32_t*)(sm + A0_OFF))[row * A0_PITCH_U32 + ku];
                }

            float D[8][4];
            #pragma unroll
            for (int j = 0; j < 8; ++j) {
                const float2 p0 = *(const float2*)((const float*)(sm + BIAS0_OFF) + j * 8 + tg * 2);
                const float2 p1 = *(const float2*)((const float*)(sm + BIAS1_OFF) + j * 8 + tg * 2);
                D[j][0] = p0.x + p1.x; D[j][1] = p0.y + p1.y;
                D[j][2] = D[j][0];     D[j][3] = D[j][1];
            }
            // layer0 (single fp16 pass)
            #pragma unroll
            for (int ks = 0; ks < 2; ++ks)
                #pragma unroll
                for (int j = 0; j < 8; ++j) mma_fp16(D[j], ah[ks], bf[(ks * 8 + j) * 32 + lane]);

            // relu -> layer1 A fragments (register-resident, D layout == A layout)
            uint32_t bh[4][4];
            #pragma unroll
            for (int i = 0; i < 4; ++i)
                #pragma unroll
                for (int rr = 0; rr < 4; ++rr) {
                    const int jt = 2 * i + (rr >> 1);
                    const float f0 = fmaxf(D[jt][(rr & 1) * 2 + 0], 0.f);
                    const float f1 = fmaxf(D[jt][(rr & 1) * 2 + 1], 0.f);
                    bh[i][rr] = packh2(f0, f1);
                }

            #pragma unroll
            for (int j = 0; j < 8; ++j) {
                const float2 bp = *(const float2*)((const float*)(sm + B1S_OFF) + j * 8 + tg * 2);
                D[j][0] = bp.x; D[j][1] = bp.y; D[j][2] = bp.x; D[j][3] = bp.y;
            }
            // layer1 (single fp16 pass)
            #pragma unroll
            for (int ks = 0; ks < 4; ++ks)
                #pragma unroll
                for (int j = 0; j < 8; ++j) mma_fp16(D[j], bh[ks], bf[(16 + ks * 8 + j) * 32 + lane]);

            // layer2 partials (relu folded; b1 already in accumulator)
            #pragma unroll
            for (int j = 0; j < 8; ++j) {
                const float4 wa = ((const float4*)(sm + W2S_OFF))[j * 8 + tg * 2];
                const float4 wb = ((const float4*)(sm + W2S_OFF))[j * 8 + tg * 2 + 1];
                const float h00 = fmaxf(D[j][0], 0.f), h01 = fmaxf(D[j][1], 0.f);
                const float h10 = fmaxf(D[j][2], 0.f), h11 = fmaxf(D[j][3], 0.f);
                pc[mt][0][0] += h00 * wa.x + h01 * wb.x;
                pc[mt][0][1] += h00 * wa.y + h01 * wb.y;
                pc[mt][0][2] += h00 * wa.z + h01 * wb.z;
                pc[mt][1][0] += h10 * wa.x + h11 * wb.x;
                pc[mt][1][1] += h10 * wa.y + h11 * wb.y;
                pc[mt][1][2] += h10 * wa.z + h11 * wb.z;
            }
        }

        // reduce partials over the 4 threads sharing each point
        #pragma unroll
        for (int a = 0; a < 2; ++a)
            #pragma unroll
            for (int q = 0; q < 2; ++q)
                #pragma unroll
                for (int c = 0; c < 3; ++c) {
                    float v = pc[a][q][c];
                    v += __shfl_xor_sync(0xffffffffu, v, 1);
                    v += __shfl_xor_sync(0xffffffffu, v, 2);
                    pc[a][q][c] = v;
                }
        float s0, s1, s2;
        if      (tg == 0) { s0 = pc[0][0][0]; s1 = pc[0][0][1]; s2 = pc[0][0][2]; }
        else if (tg == 1) { s0 = pc[0][1][0]; s1 = pc[0][1][1]; s2 = pc[0][1][2]; }
        else if (tg == 2) { s0 = pc[1][0][0]; s1 = pc[1][0][1]; s2 = pc[1][0][2]; }
        else              { s0 = pc[1][1][0]; s1 = pc[1][1][1]; s2 = pc[1][1][2]; }
        const int p = wid * 32 + ((tg >> 1) << 4) + ((tg & 1) << 3) + g;
        // compositing weight computed locally from SS0 (written pre-[B], stable here)
        float cwp;
        {
            const float* ss = (const float*)(sm + SS0_OFF);
            const float sp = ss[p] * inv_m;
            cwp = (p == 0) ? sp : (1.f - ss[p - 1] * inv_m) * sp;
        }
        const float* bb2 = (const float*)(sm + SB2_OFF);
        s0 = cwp / (1.f + __expf(-(s0 + bb2[0])));
        s1 = cwp / (1.f + __expf(-(s1 + bb2[1])));
        s2 = cwp / (1.f + __expf(-(s2 + bb2[2])));
        #pragma unroll
        for (int o = 16; o; o >>= 1) {
            s0 += __shfl_xor_sync(0xffffffffu, s0, o);
            s1 += __shfl_xor_sync(0xffffffffu, s1, o);
            s2 += __shfl_xor_sync(0xffffffffu, s2, o);
        }
        if (lane == 0) {
            float* cr = (float*)(sm + CRED_OFF);
            cr[wid * 3 + 0] = s0; cr[wid * 3 + 1] = s1; cr[wid * 3 + 2] = s2;
        }
        __syncthreads();   // [C] — protects CRED and recycles SS0/A0/BIAS for next row
        if (tid < 3) {
            const float* cr = (const float*)(sm + CRED_OFF);
            stg_ef(outCol + (long long)b * 3 + tid,
                   cr[tid] + cr[3 + tid] + cr[6 + tid] + cr[9 + tid], polF);
        }
    }
}

extern "C" void kernel_launch(void* const* d_in, const int* in_sizes, int n_in,
                              void* d_out, int out_size) {
    const int*    x  = (const int*)   d_in[0];
    const float*  d  = (const float*) d_in[1];
    const float4* gw = (const float4*)d_in[2];
    const float*  W0 = (const float*) d_in[3];
    const float*  b0 = (const float*) d_in[4];
    const float*  W1 = (const float*) d_in[5];
    const float*  b1 = (const float*) d_in[6];
    const float*  W2 = (const float*) d_in[7];
    const float*  b2 = (const float*) d_in[8];

    const int B = in_sizes[1] / DIRD;
    float* out = (float*)d_out;
    float* outSig = out;
    float* outCol = out + (long long)B * TPB;

    cudaFuncSetAttribute(surf_mma, cudaFuncAttributeMaxDynamicSharedMemorySize, SMEM_TOTAL);
    const int blocks = (B + ROWS - 1) / ROWS;
    surf_mma<<<blocks, TPB, SMEM_TOTAL>>>(x, d, gw, W0, b0, W1, b1, W2, b2,
                                          outSig, outCol, B);
}

// round 15
// speedup vs baseline: 1.0908x; 1.0908x over previous
#include <cuda_runtime.h>
#include <cuda_fp16.h>
#include <cstdint>

#define TPB  128
#define ROWS 23     // grid = ceil(16384/23) = 713 <= 148 SMs * 5 CTAs = 740 -> single wave
#define LVL  6
#define DIRD 16
#define HD   64

// ---- dynamic smem offsets (bytes) ----
#define BF_OFF    0u        // B-fragment table: 48 slots * 32 lanes * 8B = 12288
#define A0_OFF    12288u    // A0 fp16 tile: 128 rows * 80B = 10240
#define W0D_OFF   22528u    // W0 dir part fp32 [16][64] = 4096
#define W2S_OFF   26624u    // W2 as float4[64] = 1024
#define BIAS0_OFF 27648u    // bias' partial k0..7 (+b0) fp32[64]
#define BIAS1_OFF 27904u    // bias' partial k8..15 fp32[64]
#define B0S_OFF   28160u
#define B1S_OFF   28416u
#define SS0_OFF   28672u    // fp32[128]
#define WRED_OFF  29184u    // fp32[4]
#define CRED_OFF  29200u    // fp32[12]
#define SB2_OFF   29248u    // fp32[4]
#define STG_OFF   29264u    // gather staging: 128 threads * 112B (6 x float4, padded) = 14336
#define SMEM_TOTAL 43600u

#define STG_STRIDE 112      // 7*16B: conflict-free LDS.128 read-back
#define A0_PITCH_U32 20     // 80B pitch (conflict-free fragment loads)

__device__ __forceinline__ uint32_t packh2(float f0, float f1) {
    __half2 h = __floats2half2_rn(f0, f1);
    return *(uint32_t*)&h;
}

__device__ __forceinline__ uint32_t smem_u32(const void* p) {
    uint32_t a;
    asm("{ .reg .u64 t; cvta.to.shared.u64 t, %1; cvt.u32.u64 %0, t; }" : "=r"(a) : "l"(p));
    return a;
}

__device__ __forceinline__ void mma_fp16(float d[4], const uint32_t a[4], uint2 b) {
    asm volatile("mma.sync.aligned.m16n8k16.row.col.f32.f16.f16.f32 "
        "{%0,%1,%2,%3}, {%4,%5,%6,%7}, {%8,%9}, {%0,%1,%2,%3};"
        : "+f"(d[0]), "+f"(d[1]), "+f"(d[2]), "+f"(d[3])
        : "r"(a[0]), "r"(a[1]), "r"(a[2]), "r"(a[3]), "r"(b.x), "r"(b.y));
}

// eviction-policy registers (createpolicy + cache_hint form)
__device__ __forceinline__ uint64_t mk_policy_evict_last() {
    uint64_t p;
    asm("createpolicy.fractional.L2::evict_last.b64 %0, 1.0;" : "=l"(p));
    return p;
}
__device__ __forceinline__ uint64_t mk_policy_evict_first() {
    uint64_t p;
    asm("createpolicy.fractional.L2::evict_first.b64 %0, 1.0;" : "=l"(p));
    return p;
}

__device__ __forceinline__ int2 ldg_ef_v2(const int* p, uint64_t pol) {
    int2 v;
    asm volatile("ld.global.nc.L2::cache_hint.v2.s32 {%0, %1}, [%2], %3;"
                 : "=r"(v.x), "=r"(v.y) : "l"(p), "l"(pol));
    return v;
}
// streaming stores: evict_first so outputs never displace the gather table
__device__ __forceinline__ void stg_ef(float* p, float v, uint64_t pol) {
    asm volatile("st.global.L2::cache_hint.f32 [%0], %1, %2;"
                 :: "l"(p), "f"(v), "l"(pol) : "memory");
}

// async 16B gather: global->smem, no register residency, L1 bypass, table pinned in L2
__device__ __forceinline__ void cpa16(uint32_t saddr, const void* g, uint64_t pol) {
    asm volatile("cp.async.cg.shared.global.L2::cache_hint [%0], [%1], 16, %2;"
                 :: "r"(saddr), "l"(g), "l"(pol) : "memory");
}
#define CPA_COMMIT() asm volatile("cp.async.commit_group;" ::: "memory")
#define CPA_WAIT0()  asm volatile("cp.async.wait_group 0;" ::: "memory")

__device__ __forceinline__ void load_idx(const int* __restrict__ xp, int* idx, uint64_t pol) {
    const int2 a = ldg_ef_v2(xp, pol);
    const int2 b = ldg_ef_v2(xp + 2, pol);
    const int2 c = ldg_ef_v2(xp + 4, pol);
    idx[0] = a.x; idx[1] = a.y; idx[2] = b.x; idx[3] = b.y; idx[4] = c.x; idx[5] = c.y;
}

__device__ __forceinline__ void gather6_async(const float4* __restrict__ gw,
                                              const int* idx, uint32_t stg, uint64_t pol) {
    #pragma unroll
    for (int l = 0; l < LVL; ++l) cpa16(stg + l * 16, gw + idx[l], pol);
    CPA_COMMIT();
}

__global__ __launch_bounds__(TPB, 5) void surf_mma(
    const int*    __restrict__ x,
    const float*  __restrict__ dirs,
    const float4* __restrict__ gw,
    const float*  __restrict__ W0, const float* __restrict__ b0,
    const float*  __restrict__ W1, const float* __restrict__ b1,
    const float*  __restrict__ W2, const float* __restrict__ b2,
    float* __restrict__ outSig, float* __restrict__ outCol, int Btot)
{
    extern __shared__ char sm[];
    const int tid = threadIdx.x, lane = tid & 31, wid = tid >> 5;
    const int g = lane >> 2, tg = lane & 3;
    const uint64_t polL = mk_policy_evict_last();
    const uint64_t polF = mk_policy_evict_first();
    const uint32_t stg = smem_u32(sm + STG_OFF) + tid * STG_STRIDE;

    // ================= one-time staging per CTA =================
    for (int i = tid; i < DIRD * HD; i += TPB)
        ((float*)(sm + W0D_OFF))[i] = W0[i];
    if (tid < HD) {
        float4 v; v.x = W2[tid * 3]; v.y = W2[tid * 3 + 1]; v.z = W2[tid * 3 + 2]; v.w = 0.f;
        ((float4*)(sm + W2S_OFF))[tid] = v;
        ((float*)(sm + B0S_OFF))[tid] = b0[tid];
        ((float*)(sm + B1S_OFF))[tid] = b1[tid];
    }
    if (tid < 3) ((float*)(sm + SB2_OFF))[tid] = b2[tid];

    // B fragments (fp16): layer0 slots 0..15 (ks*8+j), layer1 slots 16..47 (16+ks*8+j)
    uint2* bf = (uint2*)(sm + BF_OFF);
    for (int e = tid; e < 48 * 32; e += TPB) {
        const int s = e >> 5, ln = e & 31;
        const int lg = ln >> 2, ltg = ln & 3;
        int layer, ks, j;
        if (s < 16) { layer = 0; ks = s >> 3; j = s & 7; }
        else { const int t2 = s - 16; layer = 1; ks = t2 >> 3; j = t2 & 7; }
        const int n = j * 8 + lg;
        uint32_t regs[2];
        #pragma unroll
        for (int rr = 0; rr < 2; ++rr) {
            const int k0 = ks * 16 + ltg * 2 + rr * 8;
            float wa, wb;
            if (layer == 0) {
                wa = (k0     < 18) ? W0[(16 + k0)     * HD + n] : 0.f;
                wb = (k0 + 1 < 18) ? W0[(16 + k0 + 1) * HD + n] : 0.f;
            } else {
                wa = W1[k0 * HD + n];
                wb = W1[(k0 + 1) * HD + n];
            }
            regs[rr] = packh2(wa, wb);
        }
        uint2 v; v.x = regs[0]; v.y = regs[1];
        bf[s * 32 + ln] = v;
    }
    // zero A0 pad columns 18..31 (u32 idx 9..15)
    for (int e = tid; e < TPB * 7; e += TPB) {
        const int p = e / 7, kk = 9 + (e % 7);
        ((uint32_t*)(sm + A0_OFF))[p * A0_PITCH_U32 + kk] = 0u;
    }
    __syncthreads();

    // ================= pipelined row loop (2 barriers/row) =================
    const int bBase = blockIdx.x * ROWS;
    int nidx[LVL];
    {
        const int b0r = (bBase < Btot) ? bBase : (Btot - 1);
        load_idx(x + ((long long)b0r * TPB + tid) * LVL, nidx, polF);
        gather6_async(gw, nidx, stg, polL);
    }

    for (int r = 0; r < ROWS; ++r) {
        int b = bBase + r;
        if (b >= Btot) b = Btot - 1;   // duplicated identical work; uniform barriers

        // prefetch next row's indices early (consumed after the read-back below)
        const bool more = (r + 1 < ROWS);
        if (more) {
            int bn = bBase + r + 1;
            if (bn >= Btot) bn = Btot - 1;
            load_idx(x + ((long long)bn * TPB + tid) * LVL, nidx, polF);
        }

        // ---- wait for own staged gathers; read them back ----
        CPA_WAIT0();
        float s = 1.f;
        {
            const float4* st4 = (const float4*)(sm + STG_OFF + tid * STG_STRIDE);
            // density from fp32 channel-0 (exact) + A0 pack in one pass
            uint32_t* ar = (uint32_t*)(sm + A0_OFF) + tid * A0_PITCH_U32;
            #pragma unroll
            for (int t = 0; t < 3; ++t) {
                const float4 a0 = st4[2 * t];
                const float4 a1 = st4[2 * t + 1];
                s *= fminf(fmaxf(a0.x, 0.f), 1.f) * fminf(fmaxf(a1.x, 0.f), 1.f);
                ar[3 * t + 0] = packh2(a0.y, a0.z);
                ar[3 * t + 1] = packh2(a0.w, a1.y);
                ar[3 * t + 2] = packh2(a1.z, a1.w);
            }
        }
        // staging slots fully consumed (all LDS completed — their results fed the
        // STS above). Issue next row's gathers NOW: they gain the shfl-max chain,
        // bias chain, and barrier-skew time as extra flight. Waited at next row top.
        if (more) gather6_async(gw, nidx, stg, polL);

        s += 1e-4f;
        ((float*)(sm + SS0_OFF))[tid] = s;
        float m = s;
        #pragma unroll
        for (int o = 16; o; o >>= 1) m = fmaxf(m, __shfl_xor_sync(0xffffffffu, m, o));
        if (lane == 0) ((float*)(sm + WRED_OFF))[wid] = m;

        // ---- bias' split across all 128 threads (two k-halves) ----
        {
            const int half = tid >> 6, n = tid & 63;
            float acc = half ? 0.f : ((const float*)(sm + B0S_OFF))[n];
            const float* wd = (const float*)(sm + W0D_OFF);
            const float* dp = dirs + b * DIRD + half * 8;
            #pragma unroll
            for (int k = 0; k < 8; ++k)
                acc += __ldg(dp + k) * wd[(half * 8 + k) * HD + n];
            ((float*)(sm + (half ? BIAS1_OFF : BIAS0_OFF)))[n] = acc;
        }
        __syncthreads();   // [B] — the only mid-row barrier

        // ---- sigma finalize (uses warp maxes published pre-[B]) ----
        float inv_m;
        {
            const float* wr = (const float*)(sm + WRED_OFF);
            const float mm = fmaxf(fmaxf(wr[0], wr[1]), fmaxf(wr[2], wr[3]));
            inv_m = 1.f / mm;
        }
        stg_ef(outSig + (long long)b * TPB + tid, s * inv_m, polF);

        // ================= per-warp GEMM chain (32 points/warp) =================
        float pc[2][2][3];
        #pragma unroll
        for (int a = 0; a < 2; ++a)
            #pragma unroll
            for (int q = 0; q < 2; ++q) { pc[a][q][0] = 0.f; pc[a][q][1] = 0.f; pc[a][q][2] = 0.f; }

        #pragma unroll
        for (int mt = 0; mt < 2; ++mt) {
            const int P0 = wid * 32 + mt * 16;

            uint32_t ah[2][4];
            #pragma unroll
            for (int ks = 0; ks < 2; ++ks)
                #pragma unroll
                for (int rr = 0; rr < 4; ++rr) {
                    const int row = P0 + g + ((rr & 1) << 3);
                    const int ku  = ks * 8 + tg + ((rr >> 1) << 2);
                    ah[ks][rr] = ((const uint32_t*)(sm + A0_OFF))[row * A0_PITCH_U32 + ku];
                }

            float D[8][4];
            #pragma unroll
            for (int j = 0; j < 8; ++j) {
                const float2 p0 = *(const float2*)((const float*)(sm + BIAS0_OFF) + j * 8 + tg * 2);
                const float2 p1 = *(const float2*)((const float*)(sm + BIAS1_OFF) + j * 8 + tg * 2);
                D[j][0] = p0.x + p1.x; D[j][1] = p0.y + p1.y;
                D[j][2] = D[j][0];     D[j][3] = D[j][1];
            }
            // layer0 (single fp16 pass)
            #pragma unroll
            for (int ks = 0; ks < 2; ++ks)
                #pragma unroll
                for (int j = 0; j < 8; ++j) mma_fp16(D[j], ah[ks], bf[(ks * 8 + j) * 32 + lane]);

            // relu -> layer1 A fragments (register-resident, D layout == A layout)
            uint32_t bh[4][4];
            #pragma unroll
            for (int i = 0; i < 4; ++i)
                #pragma unroll
                for (int rr = 0; rr < 4; ++rr) {
                    const int jt = 2 * i + (rr >> 1);
                    const float f0 = fmaxf(D[jt][(rr & 1) * 2 + 0], 0.f);
                    const float f1 = fmaxf(D[jt][(rr & 1) * 2 + 1], 0.f);
                    bh[i][rr] = packh2(f0, f1);
                }

            #pragma unroll
            for (int j = 0; j < 8; ++j) {
                const float2 bp = *(const float2*)((const float*)(sm + B1S_OFF) + j * 8 + tg * 2);
                D[j][0] = bp.x; D[j][1] = bp.y; D[j][2] = bp.x; D[j][3] = bp.y;
            }
            // layer1 (single fp16 pass)
            #pragma unroll
            for (int ks = 0; ks < 4; ++ks)
                #pragma unroll
                for (int j = 0; j < 8; ++j) mma_fp16(D[j], bh[ks], bf[(16 + ks * 8 + j) * 32 + lane]);

            // layer2 partials (relu folded; b1 already in accumulator)
            #pragma unroll
            for (int j = 0; j < 8; ++j) {
                const float4 wa = ((const float4*)(sm + W2S_OFF))[j * 8 + tg * 2];
                const float4 wb = ((const float4*)(sm + W2S_OFF))[j * 8 + tg * 2 + 1];
                const float h00 = fmaxf(D[j][0], 0.f), h01 = fmaxf(D[j][1], 0.f);
                const float h10 = fmaxf(D[j][2], 0.f), h11 = fmaxf(D[j][3], 0.f);
                pc[mt][0][0] += h00 * wa.x + h01 * wb.x;
                pc[mt][0][1] += h00 * wa.y + h01 * wb.y;
                pc[mt][0][2] += h00 * wa.z + h01 * wb.z;
                pc[mt][1][0] += h10 * wa.x + h11 * wb.x;
                pc[mt][1][1] += h10 * wa.y + h11 * wb.y;
                pc[mt][1][2] += h10 * wa.z + h11 * wb.z;
            }
        }

        // reduce partials over the 4 threads sharing each point
        #pragma unroll
        for (int a = 0; a < 2; ++a)
            #pragma unroll
            for (int q = 0; q < 2; ++q)
                #pragma unroll
                for (int c = 0; c < 3; ++c) {
                    float v = pc[a][q][c];
                    v += __shfl_xor_sync(0xffffffffu, v, 1);
                    v += __shfl_xor_sync(0xffffffffu, v, 2);
                    pc[a][q][c] = v;
                }
        float s0, s1, s2;
        if      (tg == 0) { s0 = pc[0][0][0]; s1 = pc[0][0][1]; s2 = pc[0][0][2]; }
        else if (tg == 1) { s0 = pc[0][1][0]; s1 = pc[0][1][1]; s2 = pc[0][1][2]; }
        else if (tg == 2) { s0 = pc[1][0][0]; s1 = pc[1][0][1]; s2 = pc[1][0][2]; }
        else              { s0 = pc[1][1][0]; s1 = pc[1][1][1]; s2 = pc[1][1][2]; }
        const int p = wid * 32 + ((tg >> 1) << 4) + ((tg & 1) << 3) + g;
        // compositing weight computed locally from SS0 (written pre-[B], stable here)
        float cwp;
        {
            const float* ss = (const float*)(sm + SS0_OFF);
            const float sp = ss[p] * inv_m;
            cwp = (p == 0) ? sp : (1.f - ss[p - 1] * inv_m) * sp;
        }
        const float* bb2 = (const float*)(sm + SB2_OFF);
        s0 = cwp / (1.f + __expf(-(s0 + bb2[0])));
        s1 = cwp / (1.f + __expf(-(s1 + bb2[1])));
        s2 = cwp / (1.f + __expf(-(s2 + bb2[2])));
        #pragma unroll
        for (int o = 16; o; o >>= 1) {
            s0 += __shfl_xor_sync(0xffffffffu, s0, o);
            s1 += __shfl_xor_sync(0xffffffffu, s1, o);
            s2 += __shfl_xor_sync(0xffffffffu, s2, o);
        }
        if (lane == 0) {
            float* cr = (float*)(sm + CRED_OFF);
            cr[wid * 3 + 0] = s0; cr[wid * 3 + 1] = s1; cr[wid * 3 + 2] = s2;
        }
        __syncthreads();   // [C] — protects CRED and recycles SS0/A0/BIAS for next row
        if (tid < 3) {
            const float* cr = (const float*)(sm + CRED_OFF);
            stg_ef(outCol + (long long)b * 3 + tid,
                   cr[tid] + cr[3 + tid] + cr[6 + tid] + cr[9 + tid], polF);
        }
    }
}

extern "C" void kernel_launch(void* const* d_in, const int* in_sizes, int n_in,
                              void* d_out, int out_size) {
    const int*    x  = (const int*)   d_in[0];
    const float*  d  = (const float*) d_in[1];
    const float4* gw = (const float4*)d_in[2];
    const float*  W0 = (const float*) d_in[3];
    const float*  b0 = (const float*) d_in[4];
    const float*  W1 = (const float*) d_in[5];
    const float*  b1 = (const float*) d_in[6];
    const float*  W2 = (const float*) d_in[7];
    const float*  b2 = (const float*) d_in[8];

    const int B = in_sizes[1] / DIRD;
    float* out = (float*)d_out;
    float* outSig = out;
    float* outCol = out + (long long)B * TPB;

    cudaFuncSetAttribute(surf_mma, cudaFuncAttributeMaxDynamicSharedMemorySize, SMEM_TOTAL);
    const int blocks = (B + ROWS - 1) / ROWS;
    surf_mma<<<blocks, TPB, SMEM_TOTAL>>>(x, d, gw, W0, b0, W1, b1, W2, b2,
                                          outSig, outCol, B);
}

// round 17
// speedup vs baseline: 1.0985x; 1.0071x over previous
#include <cuda_runtime.h>
#include <cuda_fp16.h>
#include <cstdint>

#define TPB  128
#define ROWS 23     // grid = ceil(16384/23) = 713 <= 148 SMs * 5 CTAs = 740 -> single wave
#define LVL  6
#define DIRD 16
#define HD   64

// ---- dynamic smem offsets (bytes) ----
#define BF_OFF    0u        // B-fragment table: 48 slots * 32 lanes * 8B = 12288
#define A0_OFF    12288u    // A0 fp16 tile: 128 rows * 80B = 10240
#define W0D_OFF   22528u    // W0 dir part fp32 [16][64] = 4096
#define W2S_OFF   26624u    // W2 as float4[64] = 1024
#define BIAS0_OFF 27648u    // bias' partial k0..7 (+b0) fp32[64]
#define BIAS1_OFF 27904u    // bias' partial k8..15 fp32[64]
#define B0S_OFF   28160u
#define B1S_OFF   28416u
#define SS0_OFF   28672u    // fp32[128]
#define WRED_OFF  29184u    // fp32[4]
#define CRED_OFF  29200u    // fp32[12]
#define SB2_OFF   29248u    // fp32[4]
#define STG_OFF   29264u    // gather staging: 128 threads * 112B (6 x float4, padded) = 14336
#define SMEM_TOTAL 43600u

#define STG_STRIDE 112      // 7*16B: conflict-free LDS.128 read-back
#define A0_PITCH_U32 20     // 80B pitch (conflict-free fragment loads)

__device__ __forceinline__ uint32_t packh2(float f0, float f1) {
    __half2 h = __floats2half2_rn(f0, f1);
    return *(uint32_t*)&h;
}

__device__ __forceinline__ uint32_t smem_u32(const void* p) {
    uint32_t a;
    asm("{ .reg .u64 t; cvta.to.shared.u64 t, %1; cvt.u32.u64 %0, t; }" : "=r"(a) : "l"(p));
    return a;
}

__device__ __forceinline__ void mma_fp16(float d[4], const uint32_t a[4], uint2 b) {
    asm volatile("mma.sync.aligned.m16n8k16.row.col.f32.f16.f16.f32 "
        "{%0,%1,%2,%3}, {%4,%5,%6,%7}, {%8,%9}, {%0,%1,%2,%3};"
        : "+f"(d[0]), "+f"(d[1]), "+f"(d[2]), "+f"(d[3])
        : "r"(a[0]), "r"(a[1]), "r"(a[2]), "r"(a[3]), "r"(b.x), "r"(b.y));
}

// eviction-policy registers (createpolicy + cache_hint form)
__device__ __forceinline__ uint64_t mk_policy_evict_last() {
    uint64_t p;
    asm("createpolicy.fractional.L2::evict_last.b64 %0, 1.0;" : "=l"(p));
    return p;
}
__device__ __forceinline__ uint64_t mk_policy_evict_first() {
    uint64_t p;
    asm("createpolicy.fractional.L2::evict_first.b64 %0, 1.0;" : "=l"(p));
    return p;
}

__device__ __forceinline__ int2 ldg_ef_v2(const int* p, uint64_t pol) {
    int2 v;
    asm volatile("ld.global.nc.L2::cache_hint.v2.s32 {%0, %1}, [%2], %3;"
                 : "=r"(v.x), "=r"(v.y) : "l"(p), "l"(pol));
    return v;
}
__device__ __forceinline__ float4 ldg_ef_v4f(const float* p, uint64_t pol) {
    float4 v;
    asm volatile("ld.global.nc.L2::cache_hint.v4.f32 {%0, %1, %2, %3}, [%4], %5;"
                 : "=f"(v.x), "=f"(v.y), "=f"(v.z), "=f"(v.w) : "l"(p), "l"(pol));
    return v;
}
// streaming stores: evict_first so outputs never displace the gather table
__device__ __forceinline__ void stg_ef(float* p, float v, uint64_t pol) {
    asm volatile("st.global.L2::cache_hint.f32 [%0], %1, %2;"
                 :: "l"(p), "f"(v), "l"(pol) : "memory");
}

// async 16B gather: global->smem, no register residency, L1 bypass, table pinned in L2
__device__ __forceinline__ void cpa16(uint32_t saddr, const void* g, uint64_t pol) {
    asm volatile("cp.async.cg.shared.global.L2::cache_hint [%0], [%1], 16, %2;"
                 :: "r"(saddr), "l"(g), "l"(pol) : "memory");
}
#define CPA_COMMIT() asm volatile("cp.async.commit_group;" ::: "memory")
#define CPA_WAIT0()  asm volatile("cp.async.wait_group 0;" ::: "memory")

__device__ __forceinline__ void load_idx(const int* __restrict__ xp, int* idx, uint64_t pol) {
    const int2 a = ldg_ef_v2(xp, pol);
    const int2 b = ldg_ef_v2(xp + 2, pol);
    const int2 c = ldg_ef_v2(xp + 4, pol);
    idx[0] = a.x; idx[1] = a.y; idx[2] = b.x; idx[3] = b.y; idx[4] = c.x; idx[5] = c.y;
}

__device__ __forceinline__ void gather6_async(const float4* __restrict__ gw,
                                              const int* idx, uint32_t stg, uint64_t pol) {
    #pragma unroll
    for (int l = 0; l < LVL; ++l) cpa16(stg + l * 16, gw + idx[l], pol);
    CPA_COMMIT();
}

__global__ __launch_bounds__(TPB, 5) void surf_mma(
    const int*    __restrict__ x,
    const float*  __restrict__ dirs,
    const float4* __restrict__ gw,
    const float*  __restrict__ W0, const float* __restrict__ b0,
    const float*  __restrict__ W1, const float* __restrict__ b1,
    const float*  __restrict__ W2, const float* __restrict__ b2,
    float* __restrict__ outSig, float* __restrict__ outCol, int Btot)
{
    extern __shared__ char sm[];
    const int tid = threadIdx.x, lane = tid & 31, wid = tid >> 5;
    const int g = lane >> 2, tg = lane & 3;
    const uint64_t polL = mk_policy_evict_last();
    const uint64_t polF = mk_policy_evict_first();
    const uint32_t stg = smem_u32(sm + STG_OFF) + tid * STG_STRIDE;
    const int half = tid >> 6, hn = tid & 63;   // bias-chain split

    // ================= one-time staging per CTA =================
    for (int i = tid; i < DIRD * HD; i += TPB)
        ((float*)(sm + W0D_OFF))[i] = W0[i];
    if (tid < HD) {
        float4 v; v.x = W2[tid * 3]; v.y = W2[tid * 3 + 1]; v.z = W2[tid * 3 + 2]; v.w = 0.f;
        ((float4*)(sm + W2S_OFF))[tid] = v;
        ((float*)(sm + B0S_OFF))[tid] = b0[tid];
        ((float*)(sm + B1S_OFF))[tid] = b1[tid];
    }
    if (tid < 3) ((float*)(sm + SB2_OFF))[tid] = b2[tid];

    // B fragments (fp16): layer0 slots 0..15 (ks*8+j), layer1 slots 16..47 (16+ks*8+j)
    uint2* bf = (uint2*)(sm + BF_OFF);
    for (int e = tid; e < 48 * 32; e += TPB) {
        const int s = e >> 5, ln = e & 31;
        const int lg = ln >> 2, ltg = ln & 3;
        int layer, ks, j;
        if (s < 16) { layer = 0; ks = s >> 3; j = s & 7; }
        else { const int t2 = s - 16; layer = 1; ks = t2 >> 3; j = t2 & 7; }
        const int n = j * 8 + lg;
        uint32_t regs[2];
        #pragma unroll
        for (int rr = 0; rr < 2; ++rr) {
            const int k0 = ks * 16 + ltg * 2 + rr * 8;
            float wa, wb;
            if (layer == 0) {
                wa = (k0     < 18) ? W0[(16 + k0)     * HD + n] : 0.f;
                wb = (k0 + 1 < 18) ? W0[(16 + k0 + 1) * HD + n] : 0.f;
            } else {
                wa = W1[k0 * HD + n];
                wb = W1[(k0 + 1) * HD + n];
            }
            regs[rr] = packh2(wa, wb);
        }
        uint2 v; v.x = regs[0]; v.y = regs[1];
        bf[s * 32 + ln] = v;
    }
    // zero A0 pad columns 18..31 (u32 idx 9..15)
    for (int e = tid; e < TPB * 7; e += TPB) {
        const int p = e / 7, kk = 9 + (e % 7);
        ((uint32_t*)(sm + A0_OFF))[p * A0_PITCH_U32 + kk] = 0u;
    }
    __syncthreads();

    // ================= pipelined row loop (2 barriers/row) =================
    const int bBase = blockIdx.x * ROWS;
    int nidx[LVL];
    {
        const int b0r = (bBase < Btot) ? bBase : (Btot - 1);
        load_idx(x + ((long long)b0r * TPB + tid) * LVL, nidx, polF);
        gather6_async(gw, nidx, stg, polL);
    }

    for (int r = 0; r < ROWS; ++r) {
        int b = bBase + r;
        if (b >= Btot) b = Btot - 1;   // duplicated identical work; uniform barriers

        // hoist this row's dirs loads to row top: latency overlaps CPA_WAIT0 +
        // readback + shfl chain instead of sitting raw before [B]. Short-lived regs.
        float4 dv0, dv1;
        {
            const float* dp = dirs + b * DIRD + half * 8;
            dv0 = ldg_ef_v4f(dp, polF);
            dv1 = ldg_ef_v4f(dp + 4, polF);
        }

        // prefetch next row's indices early (consumed after the read-back below)
        const bool more = (r + 1 < ROWS);
        if (more) {
            int bn = bBase + r + 1;
            if (bn >= Btot) bn = Btot - 1;
            load_idx(x + ((long long)bn * TPB + tid) * LVL, nidx, polF);
        }

        // ---- wait for own staged gathers; read them back ----
        CPA_WAIT0();
        float s = 1.f;
        {
            const float4* st4 = (const float4*)(sm + STG_OFF + tid * STG_STRIDE);
            // density from fp32 channel-0 (exact) + A0 pack in one pass
            uint32_t* ar = (uint32_t*)(sm + A0_OFF) + tid * A0_PITCH_U32;
            #pragma unroll
            for (int t = 0; t < 3; ++t) {
                const float4 a0 = st4[2 * t];
                const float4 a1 = st4[2 * t + 1];
                s *= fminf(fmaxf(a0.x, 0.f), 1.f) * fminf(fmaxf(a1.x, 0.f), 1.f);
                ar[3 * t + 0] = packh2(a0.y, a0.z);
                ar[3 * t + 1] = packh2(a0.w, a1.y);
                ar[3 * t + 2] = packh2(a1.z, a1.w);
            }
        }
        // staging slots fully consumed. Issue next row's gathers NOW: they gain the
        // shfl-max chain, bias chain, and barrier-skew time as extra flight.
        if (more) gather6_async(gw, nidx, stg, polL);

        s += 1e-4f;
        ((float*)(sm + SS0_OFF))[tid] = s;
        float m = s;
        #pragma unroll
        for (int o = 16; o; o >>= 1) m = fmaxf(m, __shfl_xor_sync(0xffffffffu, m, o));
        if (lane == 0) ((float*)(sm + WRED_OFF))[wid] = m;

        // ---- bias' split across all 128 threads (two k-halves), dirs pre-loaded ----
        {
            float acc = half ? 0.f : ((const float*)(sm + B0S_OFF))[hn];
            const float* wd = (const float*)(sm + W0D_OFF) + (half * 8) * HD + hn;
            acc += dv0.x * wd[0 * HD] + dv0.y * wd[1 * HD]
                 + dv0.z * wd[2 * HD] + dv0.w * wd[3 * HD]
                 + dv1.x * wd[4 * HD] + dv1.y * wd[5 * HD]
                 + dv1.z * wd[6 * HD] + dv1.w * wd[7 * HD];
            ((float*)(sm + (half ? BIAS1_OFF : BIAS0_OFF)))[hn] = acc;
        }
        __syncthreads();   // [B] — the only mid-row barrier

        // ---- sigma finalize (uses warp maxes published pre-[B]) ----
        float inv_m;
        {
            const float* wr = (const float*)(sm + WRED_OFF);
            const float mm = fmaxf(fmaxf(wr[0], wr[1]), fmaxf(wr[2], wr[3]));
            inv_m = 1.f / mm;
        }
        stg_ef(outSig + (long long)b * TPB + tid, s * inv_m, polF);

        // ================= per-warp GEMM chain (32 points/warp) =================
        float pc[2][2][3];
        #pragma unroll
        for (int a = 0; a < 2; ++a)
            #pragma unroll
            for (int q = 0; q < 2; ++q) { pc[a][q][0] = 0.f; pc[a][q][1] = 0.f; pc[a][q][2] = 0.f; }

        #pragma unroll
        for (int mt = 0; mt < 2; ++mt) {
            const int P0 = wid * 32 + mt * 16;

            uint32_t ah[2][4];
            #pragma unroll
            for (int ks = 0; ks < 2; ++ks)
                #pragma unroll
                for (int rr = 0; rr < 4; ++rr) {
                    const int row = P0 + g + ((rr & 1) << 3);
                    const int ku  = ks * 8 + tg + ((rr >> 1) << 2);
                    ah[ks][rr] = ((const uint32_t*)(sm + A0_OFF))[row * A0_PITCH_U32 + ku];
                }

            float D[8][4];
            #pragma unroll
            for (int j = 0; j < 8; ++j) {
                const float2 p0 = *(const float2*)((const float*)(sm + BIAS0_OFF) + j * 8 + tg * 2);
                const float2 p1 = *(const float2*)((const float*)(sm + BIAS1_OFF) + j * 8 + tg * 2);
                D[j][0] = p0.x + p1.x; D[j][1] = p0.y + p1.y;
                D[j][2] = D[j][0];     D[j][3] = D[j][1];
            }
            // layer0 (single fp16 pass)
            #pragma unroll
            for (int ks = 0; ks < 2; ++ks)
                #pragma unroll
                for (int j = 0; j < 8; ++j) mma_fp16(D[j], ah[ks], bf[(ks * 8 + j) * 32 + lane]);

            // relu -> layer1 A fragments (register-resident, D layout == A layout)
            uint32_t bh[4][4];
            #pragma unroll
            for (int i = 0; i < 4; ++i)
                #pragma unroll
                for (int rr = 0; rr < 4; ++rr) {
                    const int jt = 2 * i + (rr >> 1);
                    const float f0 = fmaxf(D[jt][(rr & 1) * 2 + 0], 0.f);
                    const float f1 = fmaxf(D[jt][(rr & 1) * 2 + 1], 0.f);
                    bh[i][rr] = packh2(f0, f1);
                }

            #pragma unroll
            for (int j = 0; j < 8; ++j) {
                const float2 bp = *(const float2*)((const float*)(sm + B1S_OFF) + j * 8 + tg * 2);
                D[j][0] = bp.x; D[j][1] = bp.y; D[j][2] = bp.x; D[j][3] = bp.y;
            }
            // layer1 (single fp16 pass)
            #pragma unroll
            for (int ks = 0; ks < 4; ++ks)
                #pragma unroll
                for (int j = 0; j < 8; ++j) mma_fp16(D[j], bh[ks], bf[(16 + ks * 8 + j) * 32 + lane]);

            // layer2 partials (relu folded; b1 already in accumulator)
            #pragma unroll
            for (int j = 0; j < 8; ++j) {
                const float4 wa = ((const float4*)(sm + W2S_OFF))[j * 8 + tg * 2];
                const float4 wb = ((const float4*)(sm + W2S_OFF))[j * 8 + tg * 2 + 1];
                const float h00 = fmaxf(D[j][0], 0.f), h01 = fmaxf(D[j][1], 0.f);
                const float h10 = fmaxf(D[j][2], 0.f), h11 = fmaxf(D[j][3], 0.f);
                pc[mt][0][0] += h00 * wa.x + h01 * wb.x;
                pc[mt][0][1] += h00 * wa.y + h01 * wb.y;
                pc[mt][0][2] += h00 * wa.z + h01 * wb.z;
                pc[mt][1][0] += h10 * wa.x + h11 * wb.x;
                pc[mt][1][1] += h10 * wa.y + h11 * wb.y;
                pc[mt][1][2] += h10 * wa.z + h11 * wb.z;
            }
        }

        // reduce partials over the 4 threads sharing each point
        #pragma unroll
        for (int a = 0; a < 2; ++a)
            #pragma unroll
            for (int q = 0; q < 2; ++q)
                #pragma unroll
                for (int c = 0; c < 3; ++c) {
                    float v = pc[a][q][c];
                    v += __shfl_xor_sync(0xffffffffu, v, 1);
                    v += __shfl_xor_sync(0xffffffffu, v, 2);
                    pc[a][q][c] = v;
                }
        float s0, s1, s2;
        if      (tg == 0) { s0 = pc[0][0][0]; s1 = pc[0][0][1]; s2 = pc[0][0][2]; }
        else if (tg == 1) { s0 = pc[0][1][0]; s1 = pc[0][1][1]; s2 = pc[0][1][2]; }
        else if (tg == 2) { s0 = pc[1][0][0]; s1 = pc[1][0][1]; s2 = pc[1][0][2]; }
        else              { s0 = pc[1][1][0]; s1 = pc[1][1][1]; s2 = pc[1][1][2]; }
        const int p = wid * 32 + ((tg >> 1) << 4) + ((tg & 1) << 3) + g;
        // compositing weight computed locally from SS0 (written pre-[B], stable here)
        float cwp;
        {
            const float* ss = (const float*)(sm + SS0_OFF);
            const float sp = ss[p] * inv_m;
            cwp = (p == 0) ? sp : (1.f - ss[p - 1] * inv_m) * sp;
        }
        const float* bb2 = (const float*)(sm + SB2_OFF);
        s0 = cwp / (1.f + __expf(-(s0 + bb2[0])));
        s1 = cwp / (1.f + __expf(-(s1 + bb2[1])));
        s2 = cwp / (1.f + __expf(-(s2 + bb2[2])));
        #pragma unroll
        for (int o = 16; o; o >>= 1) {
            s0 += __shfl_xor_sync(0xffffffffu, s0, o);
            s1 += __shfl_xor_sync(0xffffffffu, s1, o);
            s2 += __shfl_xor_sync(0xffffffffu, s2, o);
        }
        if (lane == 0) {
            float* cr = (float*)(sm + CRED_OFF);
            cr[wid * 3 + 0] = s0; cr[wid * 3 + 1] = s1; cr[wid * 3 + 2] = s2;
        }
        __syncthreads();   // [C] — protects CRED and recycles SS0/A0/BIAS for next row
        if (tid < 3) {
            const float* cr = (const float*)(sm + CRED_OFF);
            stg_ef(outCol + (long long)b * 3 + tid,
                   cr[tid] + cr[3 + tid] + cr[6 + tid] + cr[9 + tid], polF);
        }
    }
}

extern "C" void kernel_launch(void* const* d_in, const int* in_sizes, int n_in,
                              void* d_out, int out_size) {
    const int*    x  = (const int*)   d_in[0];
    const float*  d  = (const float*) d_in[1];
    const float4* gw = (const float4*)d_in[2];
    const float*  W0 = (const float*) d_in[3];
    const float*  b0 = (const float*) d_in[4];
    const float*  W1 = (const float*) d_in[5];
    const float*  b1 = (const float*) d_in[6];
    const float*  W2 = (const float*) d_in[7];
    const float*  b2 = (const float*) d_in[8];

    const int B = in_sizes[1] / DIRD;
    float* out = (float*)d_out;
    float* outSig = out;
    float* outCol = out + (long long)B * TPB;

    cudaFuncSetAttribute(surf_mma, cudaFuncAttributeMaxDynamicSharedMemorySize, SMEM_TOTAL);
    const int blocks = (B + ROWS - 1) / ROWS;
    surf_mma<<<blocks, TPB, SMEM_TOTAL>>>(x, d, gw, W0, b0, W1, b1, W2, b2,
                                          outSig, outCol, B);
}